// round 1
// baseline (speedup 1.0000x reference)
#include <cuda_runtime.h>

// OrdinalPooling2D: x (32,112,112,128) f32 NHWC, 2x2 stride-2 pool,
// sort 4 window values descending, dot with per-channel weights w[128,4]
// (relu + renormalize). Output (32,56,56,128) f32.

#define N_B   32
#define H_IN  112
#define W_IN  112
#define H_OUT 56
#define W_OUT 56
#define C_CH  128
#define C4    (C_CH / 4)          // 32 float4 groups per position

// total float4 outputs = 32*56*56*32 = 3,211,264
#define TOTAL_V4 (N_B * H_OUT * W_OUT * C4)
#define THREADS  256
#define BLOCKS   (TOTAL_V4 / THREADS)   // 12544, exact

__device__ __forceinline__ float ord_one(float p0, float p1, float p2, float p3,
                                         float4 w) {
    // constraint: clip negatives, renormalize
    float w0 = fmaxf(w.x, 0.0f);
    float w1 = fmaxf(w.y, 0.0f);
    float w2 = fmaxf(w.z, 0.0f);
    float w3 = fmaxf(w.w, 0.0f);
    float inv = __frcp_rn(w0 + w1 + w2 + w3);
    w0 *= inv; w1 *= inv; w2 *= inv; w3 *= inv;

    // odd-even transposition sort, descending (max first), n=4:
    // round 0: (0,1)(2,3)  round 1: (1,2)  round 2: (0,1)(2,3)  round 3: (1,2)
    float t;
#define CE(a, b) t = fmaxf(a, b); b = fminf(a, b); a = t;
    CE(p0, p1); CE(p2, p3);
    CE(p1, p2);
    CE(p0, p1); CE(p2, p3);
    CE(p1, p2);
#undef CE

    return p0 * w0 + p1 * w1 + p2 * w2 + p3 * w3;
}

__global__ __launch_bounds__(THREADS)
void ordinal_pool_kernel(const float4* __restrict__ x,
                         const float4* __restrict__ w4,   // w[C,4] => one float4 per channel
                         float4* __restrict__ out) {
    int idx = blockIdx.x * THREADS + threadIdx.x;   // [0, TOTAL_V4)

    int c4 = idx & (C4 - 1);        // float4 group within channels
    int t  = idx >> 5;              // C4 == 32
    int wo = t % W_OUT;
    t /= W_OUT;
    int ho = t % H_OUT;
    int n  = t / H_OUT;

    // input base in float4 units: ((n*H_IN + 2*ho)*W_IN + 2*wo)*C4 + c4
    long base = ((long)(n * H_IN + 2 * ho) * W_IN + 2 * wo) * C4 + c4;
    const long ROW = (long)W_IN * C4;   // one input row in float4 units

    float4 a = x[base];               // (2ho,   2wo)
    float4 b = x[base + C4];          // (2ho,   2wo+1)
    float4 c = x[base + ROW];         // (2ho+1, 2wo)
    float4 d = x[base + ROW + C4];    // (2ho+1, 2wo+1)

    // weights for channels 4*c4 .. 4*c4+3 (2KB table, L1-resident)
    int ch = c4 * 4;
    float4 wa = __ldg(&w4[ch + 0]);
    float4 wb = __ldg(&w4[ch + 1]);
    float4 wc = __ldg(&w4[ch + 2]);
    float4 wd = __ldg(&w4[ch + 3]);

    float4 o;
    o.x = ord_one(a.x, b.x, c.x, d.x, wa);
    o.y = ord_one(a.y, b.y, c.y, d.y, wb);
    o.z = ord_one(a.z, b.z, c.z, d.z, wc);
    o.w = ord_one(a.w, b.w, c.w, d.w, wd);

    // output layout (N,HO,WO,C): same linearization as idx
    out[idx] = o;
}

extern "C" void kernel_launch(void* const* d_in, const int* in_sizes, int n_in,
                              void* d_out, int out_size) {
    const float4* x  = (const float4*)d_in[0];   // x: 32*112*112*128 f32
    const float4* w4 = (const float4*)d_in[1];   // ordinal_weights: 128*4 f32
    float4* out = (float4*)d_out;

    ordinal_pool_kernel<<<BLOCKS, THREADS>>>(x, w4, out);
}

// round 3
// speedup vs baseline: 1.1039x; 1.1039x over previous
#include <cuda_runtime.h>

// OrdinalPooling2D: x (32,112,112,128) f32 NHWC, 2x2 stride-2 pool,
// sort 4 window values descending, dot with per-channel weights w[128,4]
// (relu + renormalize). Output (32,56,56,128) f32.
//
// R2 (re-bench; prior attempt hit infra failure): each thread computes 2
// adjacent output wo positions (same channels), front-batching 8 independent
// LDG.128 for ~2x memory-level parallelism, and amortizing the weight
// normalize across both positions. Streaming cache hints (no reuse).

#define N_B   32
#define H_IN  112
#define W_IN  112
#define H_OUT 56
#define W_OUT 56
#define C_CH  128
#define C4    (C_CH / 4)          // 32 float4 groups per position
#define WO2   (W_OUT / 2)         // 28 output-pair positions per row

// total thread work items = 32*56*28*32 = 1,605,632
#define TOTAL_T (N_B * H_OUT * WO2 * C4)
#define THREADS 256
#define BLOCKS  (TOTAL_T / THREADS)   // 6272, exact

// sort 4 values descending + dot with pre-normalized weights
__device__ __forceinline__ float ord_one(float p0, float p1, float p2, float p3,
                                         float w0, float w1, float w2, float w3) {
    float t;
#define CE(a, b) t = fmaxf(a, b); b = fminf(a, b); a = t;
    CE(p0, p1); CE(p2, p3);
    CE(p1, p2);
    CE(p0, p1); CE(p2, p3);
    CE(p1, p2);
#undef CE
    return p0 * w0 + p1 * w1 + p2 * w2 + p3 * w3;
}

__device__ __forceinline__ float4 ldcs4(const float4* p) {
    return __ldcs(p);
}

__global__ __launch_bounds__(THREADS)
void ordinal_pool_kernel(const float4* __restrict__ x,
                         const float4* __restrict__ w4,   // w[C,4]: one float4 per channel
                         float4* __restrict__ out) {
    int idx = blockIdx.x * THREADS + threadIdx.x;   // [0, TOTAL_T)

    int c4  = idx & (C4 - 1);
    int t   = idx >> 5;              // C4 == 32
    int wo2 = t % WO2;
    t /= WO2;
    int ho = t % H_OUT;
    int n  = t / H_OUT;

    // input base (float4 units): row 2*ho, col 4*wo2, channel-group c4
    long base = ((long)(n * H_IN + 2 * ho) * W_IN + 4 * wo2) * C4 + c4;
    const long ROW = (long)W_IN * C4;
    // output (N,HO,WO,C): positions wo = 2*wo2 and 2*wo2+1
    long oidx = ((long)(n * H_OUT + ho) * W_OUT + 2 * wo2) * C4 + c4;

    // 8 independent streaming loads, front-batched
    float4 a0 = ldcs4(x + base);
    float4 b0 = ldcs4(x + base + C4);
    float4 a1 = ldcs4(x + base + 2 * C4);
    float4 b1 = ldcs4(x + base + 3 * C4);
    float4 c0 = ldcs4(x + base + ROW);
    float4 d0 = ldcs4(x + base + ROW + C4);
    float4 c1 = ldcs4(x + base + ROW + 2 * C4);
    float4 d1 = ldcs4(x + base + ROW + 3 * C4);

    // weights for channels 4*c4 .. 4*c4+3 (2KB table, cached) — shared by both positions
    int ch = c4 * 4;
    float4 wa = __ldg(&w4[ch + 0]);
    float4 wb = __ldg(&w4[ch + 1]);
    float4 wc = __ldg(&w4[ch + 2]);
    float4 wd = __ldg(&w4[ch + 3]);

    // relu + renormalize, once per channel
#define NORM(W) { \
        W.x = fmaxf(W.x, 0.0f); W.y = fmaxf(W.y, 0.0f); \
        W.z = fmaxf(W.z, 0.0f); W.w = fmaxf(W.w, 0.0f); \
        float inv = __frcp_rn(W.x + W.y + W.z + W.w);    \
        W.x *= inv; W.y *= inv; W.z *= inv; W.w *= inv; }
    NORM(wa) NORM(wb) NORM(wc) NORM(wd)
#undef NORM

    float4 o0, o1;
    o0.x = ord_one(a0.x, b0.x, c0.x, d0.x, wa.x, wa.y, wa.z, wa.w);
    o0.y = ord_one(a0.y, b0.y, c0.y, d0.y, wb.x, wb.y, wb.z, wb.w);
    o0.z = ord_one(a0.z, b0.z, c0.z, d0.z, wc.x, wc.y, wc.z, wc.w);
    o0.w = ord_one(a0.w, b0.w, c0.w, d0.w, wd.x, wd.y, wd.z, wd.w);

    o1.x = ord_one(a1.x, b1.x, c1.x, d1.x, wa.x, wa.y, wa.z, wa.w);
    o1.y = ord_one(a1.y, b1.y, c1.y, d1.y, wb.x, wb.y, wb.z, wb.w);
    o1.z = ord_one(a1.z, b1.z, c1.z, d1.z, wc.x, wc.y, wc.z, wc.w);
    o1.w = ord_one(a1.w, b1.w, c1.w, d1.w, wd.x, wd.y, wd.z, wd.w);

    __stcs(out + oidx, o0);
    __stcs(out + oidx + C4, o1);
}

extern "C" void kernel_launch(void* const* d_in, const int* in_sizes, int n_in,
                              void* d_out, int out_size) {
    const float4* x  = (const float4*)d_in[0];   // x: 32*112*112*128 f32
    const float4* w4 = (const float4*)d_in[1];   // ordinal_weights: 128*4 f32
    float4* out = (float4*)d_out;

    ordinal_pool_kernel<<<BLOCKS, THREADS>>>(x, w4, out);
}